// round 16
// baseline (speedup 1.0000x reference)
#include <cuda_runtime.h>
#include <cuda_bf16.h>
#include <cuda_fp16.h>
#include <math.h>
#include <float.h>
#include <stdint.h>

// Problem constants
#define NB   2
#define CC   128
#define HH   64
#define WW   64
#define HS   128
#define WS   128
#define HP   62          // HH - 2
#define USZ  126         // HS - 2
#define M_R  4096        // HH*WW
#define N_S  16384       // HS*WS

// Scratch
static __device__ __half   g_Th[(size_t)NB * M_R * N_S];         // 268 MB f16 Gram matrix
static __device__ uint32_t g_Apk[(size_t)NB * (CC/2) * M_R];     // 2 MB  bf162 k-pair packed ref
static __device__ uint32_t g_Bpk[(size_t)NB * (CC/2) * N_S];     // 8 MB  bf162 k-pair packed shape
static __device__ unsigned long long g_pack[NB * HP * HP];       // packed (key|~idx) argmax

__device__ __forceinline__ void cp_async16(uint32_t smem_addr, const void* gptr) {
    asm volatile("cp.async.cg.shared.global [%0], [%1], 16;\n"
                 :: "r"(smem_addr), "l"(gptr));
}

// ---------------------------------------------------------------------------
// Kernel 0b: pack fp32 [n][c][m] -> bf162 k-pair layout [n][k2][m].
// Block 0 additionally zeroes the output scalar(s) and the packed argmax arr.
// ---------------------------------------------------------------------------
__global__ void pack_kernel(const float* __restrict__ src, uint32_t* __restrict__ dst,
                            int M, int total, float* out, int out_n) {
    if (blockIdx.x == 0) {
        for (int t = threadIdx.x; t < out_n; t += blockDim.x) out[t] = 0.0f;
        for (int t = threadIdx.x; t < NB * HP * HP; t += blockDim.x)
            g_pack[t] = 0ull;
    }
    for (int x = blockIdx.x * blockDim.x + threadIdx.x; x < total;
         x += gridDim.x * blockDim.x) {
        int m   = x % M;
        int nk2 = x / M;
        int n   = nk2 >> 6;
        int k2  = nk2 & 63;
        const float* s = src + ((size_t)(n * CC + 2 * k2)) * M + m;
        __nv_bfloat162 h = __floats2bfloat162_rn(s[0], s[M]);
        dst[x] = *(uint32_t*)&h;
    }
}

// ---------------------------------------------------------------------------
// Kernel 1: GEMM bf16 HMMA — EXACT R8 version (benched 113.9us, regs 128).
// SPITCH=136 conflict-free fragments; f16 smem-staged epilogue (single
// staging buffer in As2 area, 2 barriers per 32-row chunk).
// ---------------------------------------------------------------------------
#define BM 128
#define BN 128
#define BK2 16
#define SPITCH 136
#define CPITCH 136       // epilogue staging pitch in HALVES (272B rows)

__global__ __launch_bounds__(256) void gemm_kernel() {
    __shared__ __align__(16) uint32_t As2[2][BK2 * SPITCH];
    __shared__ __align__(16) uint32_t Bs2[2][BK2 * SPITCH];

    const int n = blockIdx.z;
    const uint32_t* Ap = g_Apk + (size_t)n * (CC / 2) * M_R;
    const uint32_t* Bp = g_Bpk + (size_t)n * (CC / 2) * N_S;
    __half*         Ct = g_Th  + (size_t)n * M_R * N_S;

    const int r0 = blockIdx.y * BM;
    const int s0 = blockIdx.x * BN;
    const int tid  = threadIdx.x;
    const int lane = tid & 31;
    const int wid  = tid >> 5;
    const int wg   = wid >> 2;
    const int warp_m = wg * 64;
    const int warp_n = (wid & 3) * 32;
    const int g    = lane >> 2;
    const int tid4 = lane & 3;

    const uint32_t sA = (uint32_t)__cvta_generic_to_shared(&As2[0][0]);
    const uint32_t sB = (uint32_t)__cvta_generic_to_shared(&Bs2[0][0]);

    auto issue = [&](int buf, int kk2) {
#pragma unroll
        for (int h = 0; h < 2; h++) {
            int ch = tid + h * 256;
            int k2 = ch >> 5;
            int m4 = (ch & 31) << 2;
            uint32_t doff = (uint32_t)((buf * BK2 * SPITCH + k2 * SPITCH + m4) * 4);
            cp_async16(sA + doff, Ap + (size_t)(kk2 + k2) * M_R + r0 + m4);
            cp_async16(sB + doff, Bp + (size_t)(kk2 + k2) * N_S + s0 + m4);
        }
        asm volatile("cp.async.commit_group;\n" ::: "memory");
    };

    float acc[4][4][4];
#pragma unroll
    for (int mt = 0; mt < 4; mt++)
#pragma unroll
        for (int nt = 0; nt < 4; nt++)
#pragma unroll
            for (int q = 0; q < 4; q++) acc[mt][nt][q] = 0.0f;

    issue(0, 0);

    const int NSTAGE = (CC / 2) / BK2;
#pragma unroll
    for (int s = 0; s < NSTAGE; s++) {
        if (s + 1 < NSTAGE) {
            issue((s + 1) & 1, (s + 1) * BK2);
            asm volatile("cp.async.wait_group 1;\n" ::: "memory");
        } else {
            asm volatile("cp.async.wait_group 0;\n" ::: "memory");
        }
        __syncthreads();

        const uint32_t* Ab = &As2[s & 1][0];
        const uint32_t* Bb = &Bs2[s & 1][0];
#pragma unroll
        for (int kc2 = 0; kc2 < BK2; kc2 += 8) {
            uint32_t af[4][4], bfr[4][2];
#pragma unroll
            for (int mt = 0; mt < 4; mt++) {
                int m = warp_m + mt * 16 + g;
                af[mt][0] = Ab[(kc2 + tid4)     * SPITCH + m];
                af[mt][1] = Ab[(kc2 + tid4)     * SPITCH + m + 8];
                af[mt][2] = Ab[(kc2 + tid4 + 4) * SPITCH + m];
                af[mt][3] = Ab[(kc2 + tid4 + 4) * SPITCH + m + 8];
            }
#pragma unroll
            for (int nt = 0; nt < 4; nt++) {
                int nn = warp_n + nt * 8 + g;
                bfr[nt][0] = Bb[(kc2 + tid4)     * SPITCH + nn];
                bfr[nt][1] = Bb[(kc2 + tid4 + 4) * SPITCH + nn];
            }
#pragma unroll
            for (int mt = 0; mt < 4; mt++)
#pragma unroll
                for (int nt = 0; nt < 4; nt++) {
                    asm volatile(
                        "mma.sync.aligned.m16n8k16.row.col.f32.bf16.bf16.f32 "
                        "{%0,%1,%2,%3},{%4,%5,%6,%7},{%8,%9},{%0,%1,%2,%3};"
                        : "+f"(acc[mt][nt][0]), "+f"(acc[mt][nt][1]),
                          "+f"(acc[mt][nt][2]), "+f"(acc[mt][nt][3])
                        : "r"(af[mt][0]), "r"(af[mt][1]), "r"(af[mt][2]), "r"(af[mt][3]),
                          "r"(bfr[nt][0]), "r"(bfr[nt][1]));
                }
        }
        __syncthreads();
    }

    // ---- Epilogue (R8): stage each 32-row chunk through smem, STG.128 ----
    __half* Cs = (__half*)&As2[0][0];
#pragma unroll
    for (int mt = 0; mt < 4; mt++) {
        __syncthreads();
        const int rl0 = wg * 16 + g;
#pragma unroll
        for (int nt = 0; nt < 4; nt++) {
            int col = warp_n + nt * 8 + 2 * tid4;
            *(__half2*)&Cs[rl0 * CPITCH + col] =
                __floats2half2_rn(acc[mt][nt][0], acc[mt][nt][1]);
            *(__half2*)&Cs[(rl0 + 8) * CPITCH + col] =
                __floats2half2_rn(acc[mt][nt][2], acc[mt][nt][3]);
        }
        __syncthreads();
#pragma unroll
        for (int h = 0; h < 2; h++) {
            int c = tid + h * 256;
            int rl = c >> 4;
            int seg = c & 15;
            uint4 v = *(uint4*)&Cs[rl * CPITCH + seg * 8];
            int grow = r0 + mt * 16 + ((rl >> 4) ? 64 : 0) + (rl & 15);
            *(uint4*)(Ct + (size_t)grow * N_S + s0 + seg * 8) = v;
        }
    }
}

// ---------------------------------------------------------------------------
// Kernel 2: argmax — EXACT R15 version (benched 101.2us).
// Prefetch issued right after the entry barrier; wait_group 2 slack.
// ---------------------------------------------------------------------------
__global__ __launch_bounds__(256) void argmax_kernel() {
    __shared__ __align__(16) __half buf[5][36][128];   // 45 KB

    const int n    = blockIdx.z & 1;
    const int part = blockIdx.z >> 1;
    const int base = part * 63;           // us range [base, base+63)
    const int tid = threadIdx.x;
    const int px  = tid >> 4;
    const int sub = tid & 15;
    const int di  = px >> 2;
    const int dj  = px & 3;
    const int i0  = blockIdx.y * 4;
    const int j0  = blockIdx.x * 4;
    const int i   = i0 + di;
    const int j   = j0 + dj;
    const int vs0 = sub << 3;

    const __half* Tn = g_Th + (size_t)n * M_R * N_S;

    auto issue_srow = [&](int lr, int slot) {
        int srow = base + lr;
#pragma unroll
        for (int it = 0; it < 3; it++) {
            int c = tid + it * 256;
            if (c < 576) {
                int r36 = c >> 4;
                int seg = c & 15;
                int t = r36 / 6, w = r36 - t * 6;
                int ri = min(i0 + t, HH - 1);
                int rj = min(j0 + w, WW - 1);
                const __half* src = Tn + (size_t)(ri * WW + rj) * N_S + srow * 128 + seg * 8;
                uint32_t daddr = (uint32_t)__cvta_generic_to_shared(&buf[slot][r36][seg * 8]);
                cp_async16(daddr, src);
            }
        }
        asm volatile("cp.async.commit_group;\n" ::: "memory");
    };

    issue_srow(0, 0); issue_srow(1, 1); issue_srow(2, 2); issue_srow(3, 3);

    const __half NEG_INF = __ushort_as_half((unsigned short)0xFC00);
    const __half2 NEG2   = __halves2half2(NEG_INF, NEG_INF);
    __half best_h = NEG_INF;
    int    bidx   = 0;
    const bool tail  = (sub == 15);
    const bool valid = (i < HP) && (j < HP);

    int s0 = 0;
    for (int k = 0; k < 63; k++) {
        if (k < 61) {
            asm volatile("cp.async.wait_group 2;\n" ::: "memory");
        } else if (k == 61) {
            asm volatile("cp.async.wait_group 1;\n" ::: "memory");
        } else {
            asm volatile("cp.async.wait_group 0;\n" ::: "memory");
        }
        __syncthreads();

        if (k <= 60) {
            int sw = (s0 == 0) ? 4 : s0 - 1;
            issue_srow(k + 4, sw);
        }

        int s1 = s0 + 1; if (s1 == 5) s1 = 0;
        int s2 = s1 + 1; if (s2 == 5) s2 = 0;
        const __half* sp[3] = { &buf[s0][0][0], &buf[s1][0][0], &buf[s2][0][0] };

        __half2 S[4];
#pragma unroll
        for (int q = 0; q < 4; q++) S[q] = __float2half2_rn(0.0f);

#pragma unroll
        for (int a = 0; a < 3; a++) {
            const __half* slotp = sp[a];
#pragma unroll
            for (int b = 0; b < 3; b++) {
                const __half* p = slotp + ((di + a) * 6 + (dj + b)) * 128 + vs0;
                uint4 v = *(const uint4*)p;
                uint32_t u4 = __shfl_down_sync(0xffffffffu, v.x, 1);
                __half2 h0 = *(__half2*)&v.x;
                __half2 h1 = *(__half2*)&v.y;
                __half2 h2 = *(__half2*)&v.z;
                __half2 h3 = *(__half2*)&v.w;
                __half2 h4 = *(__half2*)&u4;
                if (b == 0) {
                    S[0] = __hadd2(S[0], h0);
                    S[1] = __hadd2(S[1], h1);
                    S[2] = __hadd2(S[2], h2);
                    S[3] = __hadd2(S[3], h3);
                } else if (b == 1) {
                    uint32_t u0 = *(uint32_t*)&h0, u1 = *(uint32_t*)&h1;
                    uint32_t u2 = *(uint32_t*)&h2, u3 = *(uint32_t*)&h3;
                    uint32_t u4b = *(uint32_t*)&h4;
                    uint32_t w0 = __byte_perm(u0, u1, 0x5432);
                    uint32_t w1 = __byte_perm(u1, u2, 0x5432);
                    uint32_t w2 = __byte_perm(u2, u3, 0x5432);
                    uint32_t w3 = __byte_perm(u3, u4b, 0x5432);
                    S[0] = __hadd2(S[0], *(__half2*)&w0);
                    S[1] = __hadd2(S[1], *(__half2*)&w1);
                    S[2] = __hadd2(S[2], *(__half2*)&w2);
                    S[3] = __hadd2(S[3], *(__half2*)&w3);
                } else {
                    S[0] = __hadd2(S[0], h1);
                    S[1] = __hadd2(S[1], h2);
                    S[2] = __hadd2(S[2], h3);
                    S[3] = __hadd2(S[3], h4);
                }
            }
        }
        if (tail) S[3] = NEG2;

        __half2 m01 = __hmax2(S[0], S[1]);
        __half2 m23 = __hmax2(S[2], S[3]);
        __half2 m   = __hmax2(m01, m23);
        __half  mh  = __hmax(__low2half(m), __high2half(m));

        if (__hgt(mh, best_h)) {
            best_h = mh;
            const int ubase = (base + k) * USZ + vs0;
            bool found = false;
#pragma unroll
            for (int q = 0; q < 4; q++) {
                if (!found && __heq(__low2half(S[q]), mh))  { bidx = ubase + 2 * q;     found = true; }
                if (!found && __heq(__high2half(S[q]), mh)) { bidx = ubase + 2 * q + 1; found = true; }
            }
        }

        s0 = s1;
    }

    float best = valid ? __half2float(best_h) : -FLT_MAX;
#pragma unroll
    for (int off = 8; off > 0; off >>= 1) {
        float ov = __shfl_xor_sync(0xffffffffu, best, off);
        int   oi = __shfl_xor_sync(0xffffffffu, bidx, off);
        if (ov > best || (ov == best && oi < bidx)) { best = ov; bidx = oi; }
    }
    if (valid && sub == 0) {
        uint32_t fb  = __float_as_uint(best);
        uint32_t key = ((int)fb < 0) ? ~fb : (fb | 0x80000000u);
        unsigned long long pk =
            ((unsigned long long)key << 32) | (uint32_t)(0xFFFFFFFFu - (uint32_t)bidx);
        atomicMax(&g_pack[(n * HP + i) * HP + j], pk);
    }
}

// ---------------------------------------------------------------------------
// Kernel 3: gather matched color patch, L1, clip, global sum.
// ---------------------------------------------------------------------------
__global__ __launch_bounds__(1024) void l1_kernel(const float* __restrict__ outf,
                                                  const float* __restrict__ colf,
                                                  float* __restrict__ dout) {
    const int i = blockIdx.x;
    const int n = blockIdx.y;

    __shared__ float l1s[HP];
    __shared__ int   uu[HP];
    if (threadIdx.x < HP) {
        l1s[threadIdx.x] = 0.0f;
        unsigned long long pk = g_pack[(n * HP + i) * HP + threadIdx.x];
        uu[threadIdx.x] = (int)(0xFFFFFFFFu - (uint32_t)(pk & 0xFFFFFFFFull));
    }
    __syncthreads();

    for (int t = threadIdx.x; t < CC * HP; t += 1024) {
        int c = t / HP;
        int j = t - c * HP;
        int u  = uu[j];
        int us = u / USZ;
        int vs = u - us * USZ;

        const float* op = outf + ((size_t)(n * CC + c) * HH + i)  * WW + j;
        const float* cp = colf + ((size_t)(n * CC + c) * HS + us) * WS + vs;

        float s = 0.0f;
#pragma unroll
        for (int a = 0; a < 3; a++)
#pragma unroll
            for (int b = 0; b < 3; b++)
                s += fabsf(op[a * WW + b] - cp[a * WS + b]);
        atomicAdd(&l1s[j], s);
    }
    __syncthreads();

    if (threadIdx.x < HP) {
        float v = fminf(fmaxf(l1s[threadIdx.x], 0.0f), 1000.0f);
        atomicAdd(dout, v);
    }
}

// ---------------------------------------------------------------------------
// Launch
// Inputs (metadata order): 0 output_feat, 1 ref_feat, 2 shape_feat, 3 color_feat
// ---------------------------------------------------------------------------
extern "C" void kernel_launch(void* const* d_in, const int* in_sizes, int n_in,
                              void* d_out, int out_size) {
    const float* output_feat = (const float*)d_in[0];
    const float* ref_feat    = (const float*)d_in[1];
    const float* shape_feat  = (const float*)d_in[2];
    const float* color_feat  = (const float*)d_in[3];
    float* out = (float*)d_out;

    pack_kernel<<<256, 256>>>(ref_feat,   g_Apk, M_R, NB * (CC / 2) * M_R,
                              out, out_size);
    pack_kernel<<<512, 256>>>(shape_feat, g_Bpk, N_S, NB * (CC / 2) * N_S,
                              out, 0);

    dim3 g1(N_S / BN, M_R / BM, NB);    // 128 x 32 x 2
    gemm_kernel<<<g1, 256>>>();

    dim3 g2(16, 16, NB * 2);
    argmax_kernel<<<g2, 256>>>();

    dim3 g3(HP, NB);
    l1_kernel<<<g3, 1024>>>(output_feat, color_feat, out);
}

// round 17
// speedup vs baseline: 1.0183x; 1.0183x over previous
#include <cuda_runtime.h>
#include <cuda_bf16.h>
#include <cuda_fp16.h>
#include <math.h>
#include <float.h>
#include <stdint.h>

// Problem constants
#define NB   2
#define CC   128
#define HH   64
#define WW   64
#define HS   128
#define WS   128
#define HP   62          // HH - 2
#define USZ  126         // HS - 2
#define M_R  4096        // HH*WW
#define N_S  16384       // HS*WS

// Scratch
static __device__ __half   g_Th[(size_t)NB * M_R * N_S];         // 268 MB f16 Gram matrix
static __device__ uint32_t g_Apk[(size_t)NB * (CC/2) * M_R];     // 2 MB  bf162 k-pair packed ref
static __device__ uint32_t g_Bpk[(size_t)NB * (CC/2) * N_S];     // 8 MB  bf162 k-pair packed shape
static __device__ unsigned long long g_pack[NB * HP * HP];       // packed (key|~idx) argmax
static __device__ float    g_l1[NB * HP * HP];                   // per-pixel L1 partials

__device__ __forceinline__ void cp_async16(uint32_t smem_addr, const void* gptr) {
    asm volatile("cp.async.cg.shared.global [%0], [%1], 16;\n"
                 :: "r"(smem_addr), "l"(gptr));
}

// ---------------------------------------------------------------------------
// Kernel 0: merged pack (A: blocks 0..255, B: blocks 256..767).
// Block 0 additionally zeroes out, g_pack, g_l1.
// ---------------------------------------------------------------------------
__global__ void pack2_kernel(const float* __restrict__ srcA, uint32_t* __restrict__ dstA,
                             const float* __restrict__ srcB, uint32_t* __restrict__ dstB,
                             float* out, int out_n) {
    const int tid = threadIdx.x;
    if (blockIdx.x == 0) {
        for (int t = tid; t < out_n; t += blockDim.x) out[t] = 0.0f;
        for (int t = tid; t < NB * HP * HP; t += blockDim.x) {
            g_pack[t] = 0ull;
            g_l1[t]   = 0.0f;
        }
    }
    if (blockIdx.x < 256) {
        const int total = NB * (CC / 2) * M_R;
        for (int x = blockIdx.x * blockDim.x + tid; x < total; x += 256 * blockDim.x) {
            int m   = x % M_R;
            int nk2 = x / M_R;
            int n   = nk2 >> 6;
            int k2  = nk2 & 63;
            const float* s = srcA + ((size_t)(n * CC + 2 * k2)) * M_R + m;
            __nv_bfloat162 h = __floats2bfloat162_rn(s[0], s[M_R]);
            dstA[x] = *(uint32_t*)&h;
        }
    } else {
        const int bx = blockIdx.x - 256;
        const int total = NB * (CC / 2) * N_S;
        for (int x = bx * blockDim.x + tid; x < total; x += 512 * blockDim.x) {
            int m   = x % N_S;
            int nk2 = x / N_S;
            int n   = nk2 >> 6;
            int k2  = nk2 & 63;
            const float* s = srcB + ((size_t)(n * CC + 2 * k2)) * N_S + m;
            __nv_bfloat162 h = __floats2bfloat162_rn(s[0], s[N_S]);
            dstB[x] = *(uint32_t*)&h;
        }
    }
}

// ---------------------------------------------------------------------------
// Kernel 1: GEMM bf16 HMMA, 4-stage full prefetch (no buffer reuse in
// mainloop -> 1 barrier per stage, no WAR stalls). SPITCH=136 conflict-free
// fragments; R8's f16 smem-staged epilogue (stages into stage-0 area).
// Dynamic smem: 2 * 4 * BK2 * SPITCH * 4 = 69632 B.
// ---------------------------------------------------------------------------
#define BM 128
#define BN 128
#define BK2 16
#define SPITCH 136
#define CPITCH 136
#define GEMM_STG 4
#define GEMM_SMEM_BYTES (2 * GEMM_STG * BK2 * SPITCH * 4)

__global__ __launch_bounds__(256) void gemm_kernel() {
    extern __shared__ __align__(16) uint32_t dynsm[];
    uint32_t* Asm = dynsm;                                // 4 A stages
    uint32_t* Bsm = dynsm + GEMM_STG * BK2 * SPITCH;      // 4 B stages

    const int n = blockIdx.z;
    const uint32_t* Ap = g_Apk + (size_t)n * (CC / 2) * M_R;
    const uint32_t* Bp = g_Bpk + (size_t)n * (CC / 2) * N_S;
    __half*         Ct = g_Th  + (size_t)n * M_R * N_S;

    const int r0 = blockIdx.y * BM;
    const int s0 = blockIdx.x * BN;
    const int tid  = threadIdx.x;
    const int lane = tid & 31;
    const int wid  = tid >> 5;
    const int wg   = wid >> 2;
    const int warp_m = wg * 64;
    const int warp_n = (wid & 3) * 32;
    const int g    = lane >> 2;
    const int tid4 = lane & 3;

    const uint32_t sA = (uint32_t)__cvta_generic_to_shared(Asm);
    const uint32_t sB = (uint32_t)__cvta_generic_to_shared(Bsm);

    // Prologue: issue ALL four stages (one commit group per stage).
#pragma unroll
    for (int s = 0; s < GEMM_STG; s++) {
#pragma unroll
        for (int h = 0; h < 2; h++) {
            int ch = tid + h * 256;
            int k2 = ch >> 5;
            int m4 = (ch & 31) << 2;
            uint32_t doff = (uint32_t)((s * BK2 * SPITCH + k2 * SPITCH + m4) * 4);
            cp_async16(sA + doff, Ap + (size_t)(s * BK2 + k2) * M_R + r0 + m4);
            cp_async16(sB + doff, Bp + (size_t)(s * BK2 + k2) * N_S + s0 + m4);
        }
        asm volatile("cp.async.commit_group;\n" ::: "memory");
    }

    float acc[4][4][4];
#pragma unroll
    for (int mt = 0; mt < 4; mt++)
#pragma unroll
        for (int nt = 0; nt < 4; nt++)
#pragma unroll
            for (int q = 0; q < 4; q++) acc[mt][nt][q] = 0.0f;

#pragma unroll
    for (int s = 0; s < GEMM_STG; s++) {
        if (s == 0)      asm volatile("cp.async.wait_group 3;\n" ::: "memory");
        else if (s == 1) asm volatile("cp.async.wait_group 2;\n" ::: "memory");
        else if (s == 2) asm volatile("cp.async.wait_group 1;\n" ::: "memory");
        else             asm volatile("cp.async.wait_group 0;\n" ::: "memory");
        __syncthreads();

        const uint32_t* Ab = Asm + s * BK2 * SPITCH;
        const uint32_t* Bb = Bsm + s * BK2 * SPITCH;
#pragma unroll
        for (int kc2 = 0; kc2 < BK2; kc2 += 8) {
            uint32_t af[4][4], bfr[4][2];
#pragma unroll
            for (int mt = 0; mt < 4; mt++) {
                int m = warp_m + mt * 16 + g;
                af[mt][0] = Ab[(kc2 + tid4)     * SPITCH + m];
                af[mt][1] = Ab[(kc2 + tid4)     * SPITCH + m + 8];
                af[mt][2] = Ab[(kc2 + tid4 + 4) * SPITCH + m];
                af[mt][3] = Ab[(kc2 + tid4 + 4) * SPITCH + m + 8];
            }
#pragma unroll
            for (int nt = 0; nt < 4; nt++) {
                int nn = warp_n + nt * 8 + g;
                bfr[nt][0] = Bb[(kc2 + tid4)     * SPITCH + nn];
                bfr[nt][1] = Bb[(kc2 + tid4 + 4) * SPITCH + nn];
            }
#pragma unroll
            for (int mt = 0; mt < 4; mt++)
#pragma unroll
                for (int nt = 0; nt < 4; nt++) {
                    asm volatile(
                        "mma.sync.aligned.m16n8k16.row.col.f32.bf16.bf16.f32 "
                        "{%0,%1,%2,%3},{%4,%5,%6,%7},{%8,%9},{%0,%1,%2,%3};"
                        : "+f"(acc[mt][nt][0]), "+f"(acc[mt][nt][1]),
                          "+f"(acc[mt][nt][2]), "+f"(acc[mt][nt][3])
                        : "r"(af[mt][0]), "r"(af[mt][1]), "r"(af[mt][2]), "r"(af[mt][3]),
                          "r"(bfr[nt][0]), "r"(bfr[nt][1]));
                }
        }
    }

    // ---- Epilogue (R8-style): stage each 32-row chunk through smem ----
    __half* Cs = (__half*)Asm;   // stage-0 area (free after barrier)
#pragma unroll
    for (int mt = 0; mt < 4; mt++) {
        __syncthreads();
        const int rl0 = wg * 16 + g;
#pragma unroll
        for (int nt = 0; nt < 4; nt++) {
            int col = warp_n + nt * 8 + 2 * tid4;
            *(__half2*)&Cs[rl0 * CPITCH + col] =
                __floats2half2_rn(acc[mt][nt][0], acc[mt][nt][1]);
            *(__half2*)&Cs[(rl0 + 8) * CPITCH + col] =
                __floats2half2_rn(acc[mt][nt][2], acc[mt][nt][3]);
        }
        __syncthreads();
#pragma unroll
        for (int h = 0; h < 2; h++) {
            int c = tid + h * 256;
            int rl = c >> 4;
            int seg = c & 15;
            uint4 v = *(uint4*)&Cs[rl * CPITCH + seg * 8];
            int grow = r0 + mt * 16 + ((rl >> 4) ? 64 : 0) + (rl & 15);
            *(uint4*)(Ct + (size_t)grow * N_S + s0 + seg * 8) = v;
        }
    }
}

// ---------------------------------------------------------------------------
// Kernel 2: argmax — EXACT R15 version (benched 101.2/101.1 us). UNTOUCHED.
// ---------------------------------------------------------------------------
__global__ __launch_bounds__(256) void argmax_kernel() {
    __shared__ __align__(16) __half buf[5][36][128];   // 45 KB

    const int n    = blockIdx.z & 1;
    const int part = blockIdx.z >> 1;
    const int base = part * 63;
    const int tid = threadIdx.x;
    const int px  = tid >> 4;
    const int sub = tid & 15;
    const int di  = px >> 2;
    const int dj  = px & 3;
    const int i0  = blockIdx.y * 4;
    const int j0  = blockIdx.x * 4;
    const int i   = i0 + di;
    const int j   = j0 + dj;
    const int vs0 = sub << 3;

    const __half* Tn = g_Th + (size_t)n * M_R * N_S;

    auto issue_srow = [&](int lr, int slot) {
        int srow = base + lr;
#pragma unroll
        for (int it = 0; it < 3; it++) {
            int c = tid + it * 256;
            if (c < 576) {
                int r36 = c >> 4;
                int seg = c & 15;
                int t = r36 / 6, w = r36 - t * 6;
                int ri = min(i0 + t, HH - 1);
                int rj = min(j0 + w, WW - 1);
                const __half* src = Tn + (size_t)(ri * WW + rj) * N_S + srow * 128 + seg * 8;
                uint32_t daddr = (uint32_t)__cvta_generic_to_shared(&buf[slot][r36][seg * 8]);
                cp_async16(daddr, src);
            }
        }
        asm volatile("cp.async.commit_group;\n" ::: "memory");
    };

    issue_srow(0, 0); issue_srow(1, 1); issue_srow(2, 2); issue_srow(3, 3);

    const __half NEG_INF = __ushort_as_half((unsigned short)0xFC00);
    const __half2 NEG2   = __halves2half2(NEG_INF, NEG_INF);
    __half best_h = NEG_INF;
    int    bidx   = 0;
    const bool tail  = (sub == 15);
    const bool valid = (i < HP) && (j < HP);

    int s0 = 0;
    for (int k = 0; k < 63; k++) {
        if (k < 61) {
            asm volatile("cp.async.wait_group 2;\n" ::: "memory");
        } else if (k == 61) {
            asm volatile("cp.async.wait_group 1;\n" ::: "memory");
        } else {
            asm volatile("cp.async.wait_group 0;\n" ::: "memory");
        }
        __syncthreads();

        if (k <= 60) {
            int sw = (s0 == 0) ? 4 : s0 - 1;
            issue_srow(k + 4, sw);
        }

        int s1 = s0 + 1; if (s1 == 5) s1 = 0;
        int s2 = s1 + 1; if (s2 == 5) s2 = 0;
        const __half* sp[3] = { &buf[s0][0][0], &buf[s1][0][0], &buf[s2][0][0] };

        __half2 S[4];
#pragma unroll
        for (int q = 0; q < 4; q++) S[q] = __float2half2_rn(0.0f);

#pragma unroll
        for (int a = 0; a < 3; a++) {
            const __half* slotp = sp[a];
#pragma unroll
            for (int b = 0; b < 3; b++) {
                const __half* p = slotp + ((di + a) * 6 + (dj + b)) * 128 + vs0;
                uint4 v = *(const uint4*)p;
                uint32_t u4 = __shfl_down_sync(0xffffffffu, v.x, 1);
                __half2 h0 = *(__half2*)&v.x;
                __half2 h1 = *(__half2*)&v.y;
                __half2 h2 = *(__half2*)&v.z;
                __half2 h3 = *(__half2*)&v.w;
                __half2 h4 = *(__half2*)&u4;
                if (b == 0) {
                    S[0] = __hadd2(S[0], h0);
                    S[1] = __hadd2(S[1], h1);
                    S[2] = __hadd2(S[2], h2);
                    S[3] = __hadd2(S[3], h3);
                } else if (b == 1) {
                    uint32_t u0 = *(uint32_t*)&h0, u1 = *(uint32_t*)&h1;
                    uint32_t u2 = *(uint32_t*)&h2, u3 = *(uint32_t*)&h3;
                    uint32_t u4b = *(uint32_t*)&h4;
                    uint32_t w0 = __byte_perm(u0, u1, 0x5432);
                    uint32_t w1 = __byte_perm(u1, u2, 0x5432);
                    uint32_t w2 = __byte_perm(u2, u3, 0x5432);
                    uint32_t w3 = __byte_perm(u3, u4b, 0x5432);
                    S[0] = __hadd2(S[0], *(__half2*)&w0);
                    S[1] = __hadd2(S[1], *(__half2*)&w1);
                    S[2] = __hadd2(S[2], *(__half2*)&w2);
                    S[3] = __hadd2(S[3], *(__half2*)&w3);
                } else {
                    S[0] = __hadd2(S[0], h1);
                    S[1] = __hadd2(S[1], h2);
                    S[2] = __hadd2(S[2], h3);
                    S[3] = __hadd2(S[3], h4);
                }
            }
        }
        if (tail) S[3] = NEG2;

        __half2 m01 = __hmax2(S[0], S[1]);
        __half2 m23 = __hmax2(S[2], S[3]);
        __half2 m   = __hmax2(m01, m23);
        __half  mh  = __hmax(__low2half(m), __high2half(m));

        if (__hgt(mh, best_h)) {
            best_h = mh;
            const int ubase = (base + k) * USZ + vs0;
            bool found = false;
#pragma unroll
            for (int q = 0; q < 4; q++) {
                if (!found && __heq(__low2half(S[q]), mh))  { bidx = ubase + 2 * q;     found = true; }
                if (!found && __heq(__high2half(S[q]), mh)) { bidx = ubase + 2 * q + 1; found = true; }
            }
        }

        s0 = s1;
    }

    float best = valid ? __half2float(best_h) : -FLT_MAX;
#pragma unroll
    for (int off = 8; off > 0; off >>= 1) {
        float ov = __shfl_xor_sync(0xffffffffu, best, off);
        int   oi = __shfl_xor_sync(0xffffffffu, bidx, off);
        if (ov > best || (ov == best && oi < bidx)) { best = ov; bidx = oi; }
    }
    if (valid && sub == 0) {
        uint32_t fb  = __float_as_uint(best);
        uint32_t key = ((int)fb < 0) ? ~fb : (fb | 0x80000000u);
        unsigned long long pk =
            ((unsigned long long)key << 32) | (uint32_t)(0xFFFFFFFFu - (uint32_t)bidx);
        atomicMax(&g_pack[(n * HP + i) * HP + j], pk);
    }
}

// ---------------------------------------------------------------------------
// Kernel 3: L1 partials, c-split x4 (grid 62 x 2 x 4, 256 thr). Each block
// handles 32 channels for one (i, n); partial per-pixel sums -> g_l1.
// ---------------------------------------------------------------------------
__global__ __launch_bounds__(256) void l1_kernel(const float* __restrict__ outf,
                                                 const float* __restrict__ colf) {
    const int i  = blockIdx.x;
    const int n  = blockIdx.y;
    const int cs = blockIdx.z;

    __shared__ float l1s[HP];
    __shared__ int   uu[HP];
    if (threadIdx.x < HP) {
        l1s[threadIdx.x] = 0.0f;
        unsigned long long pk = g_pack[(n * HP + i) * HP + threadIdx.x];
        uu[threadIdx.x] = (int)(0xFFFFFFFFu - (uint32_t)(pk & 0xFFFFFFFFull));
    }
    __syncthreads();

    for (int x = threadIdx.x; x < 32 * HP; x += 256) {
        int cl = x / HP;
        int j  = x - cl * HP;
        int c  = cs * 32 + cl;
        int u  = uu[j];
        int us = u / USZ;
        int vs = u - us * USZ;

        const float* op = outf + ((size_t)(n * CC + c) * HH + i)  * WW + j;
        const float* cp = colf + ((size_t)(n * CC + c) * HS + us) * WS + vs;

        float s = 0.0f;
#pragma unroll
        for (int a = 0; a < 3; a++)
#pragma unroll
            for (int b = 0; b < 3; b++)
                s += fabsf(op[a * WW + b] - cp[a * WS + b]);
        atomicAdd(&l1s[j], s);
    }
    __syncthreads();

    if (threadIdx.x < HP)
        atomicAdd(&g_l1[(n * HP + i) * HP + threadIdx.x], l1s[threadIdx.x]);
}

// ---------------------------------------------------------------------------
// Kernel 4: clip + global sum of the 7688 per-pixel L1 values.
// ---------------------------------------------------------------------------
__global__ __launch_bounds__(256) void clip_kernel(float* __restrict__ dout) {
    float s = 0.0f;
    for (int x = blockIdx.x * 256 + threadIdx.x; x < NB * HP * HP;
         x += gridDim.x * 256)
        s += fminf(fmaxf(g_l1[x], 0.0f), 1000.0f);
#pragma unroll
    for (int off = 16; off > 0; off >>= 1)
        s += __shfl_xor_sync(0xffffffffu, s, off);
    __shared__ float ws[8];
    if ((threadIdx.x & 31) == 0) ws[threadIdx.x >> 5] = s;
    __syncthreads();
    if (threadIdx.x < 8) {
        float v = ws[threadIdx.x];
#pragma unroll
        for (int off = 4; off > 0; off >>= 1)
            v += __shfl_xor_sync(0xffu, v, off);
        if (threadIdx.x == 0) atomicAdd(dout, v);
    }
}

// ---------------------------------------------------------------------------
// Launch
// Inputs (metadata order): 0 output_feat, 1 ref_feat, 2 shape_feat, 3 color_feat
// ---------------------------------------------------------------------------
extern "C" void kernel_launch(void* const* d_in, const int* in_sizes, int n_in,
                              void* d_out, int out_size) {
    const float* output_feat = (const float*)d_in[0];
    const float* ref_feat    = (const float*)d_in[1];
    const float* shape_feat  = (const float*)d_in[2];
    const float* color_feat  = (const float*)d_in[3];
    float* out = (float*)d_out;

    cudaFuncSetAttribute(gemm_kernel,
                         cudaFuncAttributeMaxDynamicSharedMemorySize, GEMM_SMEM_BYTES);

    pack2_kernel<<<768, 256>>>(ref_feat, g_Apk, shape_feat, g_Bpk, out, out_size);

    dim3 g1(N_S / BN, M_R / BM, NB);    // 128 x 32 x 2
    gemm_kernel<<<g1, 256, GEMM_SMEM_BYTES>>>();

    dim3 g2(16, 16, NB * 2);
    argmax_kernel<<<g2, 256>>>();

    dim3 g3(HP, NB, 4);                 // 62 x 2 x 4 (c-split)
    l1_kernel<<<g3, 256>>>(output_feat, color_feat);

    clip_kernel<<<8, 256>>>(out);
}